// round 16
// baseline (speedup 1.0000x reference)
#include <cuda_runtime.h>
#include <cuda_bf16.h>
#include <cstdint>

// Problem constants
#define KW 7
#define CC 256
#define BB 4
#define HWN 1024          // 32*32
#define NP (BB * CC)      // 1024 planes
#define PW2 40            // padded smem row stride (floats)
#define PHW2 (38 * PW2)   // 1520 floats per plane

// Scratch (device globals)
__device__ float g_q[BB * CC * HWN];
__device__ float g_k[BB * CC * HWN];
__device__ float g_v[BB * CC * HWN];
__device__ __nv_bfloat16 g_Whi[3 * 256 * 256];
__device__ __nv_bfloat16 g_Wlo[3 * 256 * 256];
__device__ __nv_bfloat16 g_Xhi[BB * 256 * 1024];
__device__ __nv_bfloat16 g_Xlo[BB * 256 * 1024];
__device__ int g_attn_ctr;   // reset by gemm block 0 each launch
__device__ int g_bar;        // convert-phase barrier; reset by attn (plane-0 stealer)

// ---------------------------------------------------------------------------
// helpers
// ---------------------------------------------------------------------------
__device__ __forceinline__ uint32_t smem_u32(const void* p) {
    uint32_t a;
    asm("{ .reg .u64 t; cvta.to.shared.u64 t, %1; cvt.u32.u64 %0, t; }" : "=r"(a) : "l"(p));
    return a;
}
__device__ __forceinline__ void ldsm_x4(uint32_t r[4], uint32_t addr) {
    asm volatile("ldmatrix.sync.aligned.m8n8.x4.shared.b16 {%0,%1,%2,%3}, [%4];"
                 : "=r"(r[0]), "=r"(r[1]), "=r"(r[2]), "=r"(r[3]) : "r"(addr));
}
__device__ __forceinline__ void ldsm_x4_t(uint32_t r[4], uint32_t addr) {
    asm volatile("ldmatrix.sync.aligned.m8n8.x4.trans.shared.b16 {%0,%1,%2,%3}, [%4];"
                 : "=r"(r[0]), "=r"(r[1]), "=r"(r[2]), "=r"(r[3]) : "r"(addr));
}
__device__ __forceinline__ void mma_bf16(float c[4], const uint32_t a[4],
                                         uint32_t b0, uint32_t b1) {
    asm volatile(
        "mma.sync.aligned.m16n8k16.row.col.f32.bf16.bf16.f32 "
        "{%0,%1,%2,%3}, {%4,%5,%6,%7}, {%8,%9}, {%0,%1,%2,%3};"
        : "+f"(c[0]), "+f"(c[1]), "+f"(c[2]), "+f"(c[3])
        : "r"(a[0]), "r"(a[1]), "r"(a[2]), "r"(a[3]), "r"(b0), "r"(b1));
}
__device__ __forceinline__ void split_bf(float a, __nv_bfloat16& h, __nv_bfloat16& l) {
    h = __float2bfloat16(a);
    l = __float2bfloat16(a - __bfloat162float(h));
}
__device__ __forceinline__ uint32_t pack2(__nv_bfloat16 a, __nv_bfloat16 b) {
    __nv_bfloat162 t; t.x = a; t.y = b;
    return *(uint32_t*)&t;
}
#define CP_ASYNC16(dst, src) \
    asm volatile("cp.async.cg.shared.global [%0], [%1], 16;" :: "r"(dst), "l"(src))
#define CP_COMMIT() asm volatile("cp.async.commit_group;" ::: "memory")
#define CP_WAIT(N)  asm volatile("cp.async.wait_group %0;" :: "n"(N) : "memory")

__device__ __forceinline__ float ex2f(float x) {
    float y;
    asm("ex2.approx.ftz.f32 %0, %1;" : "=f"(y) : "f"(x));
    return y;
}

// ---------------------------------------------------------------------------
// Fused convert + bf16 split-precision QKV GEMM.
// Phase 1: all 384 CTAs grid-stride convert x/W -> bf16 hi/lo globals.
// Phase 2: device-wide barrier (all CTAs resident: 384 <= 3*148).
// Phase 3: cp.async 2-stage pipelined GEMM, 64x128 tile, BK=32, 8 warps.
// grid: x = 96 (12 m-tiles over combined 768 rows x 8 n-tiles), y = batch(4)
// ---------------------------------------------------------------------------
#define SKA 48
#define SKB 136
#define OFF_AL 6144
#define OFF_BH 12288
#define OFF_BL 20992
#define STG_BYTES 29696
#define SMEM_TOTAL (2 * STG_BYTES)
#define N_X4 262144      // x float4 count
#define N_TOT 311296     // + W float4 count (49152)
#define N_THR 98304      // 384 * 256

__global__ __launch_bounds__(256, 3) void qkv_fused_kernel(
    const float* __restrict__ x,
    const float* __restrict__ wq,
    const float* __restrict__ wk,
    const float* __restrict__ wv)
{
    extern __shared__ char sm[];
    const uint32_t sm_base = smem_u32(sm);
    const int tid = threadIdx.x;
    const int bid = blockIdx.y * 96 + blockIdx.x;   // 0..383

    // ---- Phase 1: convert (grid-stride, MLP~3) ----
    if (bid == 0 && tid == 0) g_attn_ctr = 0;
    for (int i = bid * 256 + tid; i < N_TOT; i += N_THR) {
        __nv_bfloat16 h0, l0, h1, l1, h2, l2, h3, l3;
        if (i < N_X4) {
            float4 v = ((const float4*)x)[i];
            split_bf(v.x, h0, l0); split_bf(v.y, h1, l1);
            split_bf(v.z, h2, l2); split_bf(v.w, h3, l3);
            int base = i * 4;
            *(uint2*)&g_Xhi[base] = make_uint2(pack2(h0, h1), pack2(h2, h3));
            *(uint2*)&g_Xlo[base] = make_uint2(pack2(l0, l1), pack2(l2, l3));
        } else {
            int i4 = i - N_X4;
            int mat = i4 >> 14;
            int off4 = i4 & 16383;
            const float* Wp = (mat == 0) ? wq : (mat == 1) ? wk : wv;
            float4 v = ((const float4*)Wp)[off4];
            split_bf(v.x, h0, l0); split_bf(v.y, h1, l1);
            split_bf(v.z, h2, l2); split_bf(v.w, h3, l3);
            int base = i4 * 4;
            *(uint2*)&g_Whi[base] = make_uint2(pack2(h0, h1), pack2(h2, h3));
            *(uint2*)&g_Wlo[base] = make_uint2(pack2(l0, l1), pack2(l2, l3));
        }
    }

    // ---- Phase 2: device-wide barrier (all 384 CTAs resident in one wave) ----
    __threadfence();
    __syncthreads();
    if (tid == 0) {
        atomicAdd(&g_bar, 1);
        volatile int* vb = &g_bar;
        while (*vb < 384) __nanosleep(128);
    }
    __syncthreads();

    // ---- Phase 3: GEMM (reads via cp.async.cg -> L2-coherent) ----
    const int wid  = tid >> 5;
    const int lane = tid & 31;
    const int wm   = wid >> 2;
    const int wn   = wid & 3;
    const int b    = blockIdx.y;
    const int m0g  = (blockIdx.x >> 3) * 64;
    const int n0   = (blockIdx.x & 7) * 128;

    const int ar  = tid >> 2;
    const int ac  = (tid & 3) << 3;
    const int br  = tid >> 4;
    const int bc  = (tid & 15) << 3;

    const __nv_bfloat16* AgH = g_Whi + (size_t)(m0g + ar) * 256 + ac;
    const __nv_bfloat16* AgL = g_Wlo + (size_t)(m0g + ar) * 256 + ac;
    const __nv_bfloat16* BgH = g_Xhi + ((size_t)(b * 256 + br)) * 1024 + n0 + bc;
    const __nv_bfloat16* BgL = g_Xlo + ((size_t)(b * 256 + br)) * 1024 + n0 + bc;

    const uint32_t adst = (uint32_t)(ar * SKA + ac) * 2u;
    const uint32_t bdst = (uint32_t)(br * SKB + bc) * 2u;

    auto issue = [&](int ch) {
        const uint32_t stb = sm_base + (ch & 1) * STG_BYTES;
        const int k0 = ch * 32;
        CP_ASYNC16(stb + adst,          AgH + k0);
        CP_ASYNC16(stb + OFF_AL + adst, AgL + k0);
        #pragma unroll
        for (int t = 0; t < 2; t++) {
            uint32_t d = bdst + (uint32_t)(t * 16 * SKB) * 2u;
            CP_ASYNC16(stb + OFF_BH + d, BgH + (size_t)(k0 + t * 16) * 1024);
            CP_ASYNC16(stb + OFF_BL + d, BgL + (size_t)(k0 + t * 16) * 1024);
        }
        CP_COMMIT();
    };

    issue(0);
    issue(1);

    float acc[2][4][4];
    #pragma unroll
    for (int i = 0; i < 2; i++)
        #pragma unroll
        for (int j = 0; j < 4; j++)
            #pragma unroll
            for (int r = 0; r < 4; r++) acc[i][j][r] = 0.f;

    #pragma unroll
    for (int ch = 0; ch < 8; ch++) {
        if (ch < 7) { CP_WAIT(1); } else { CP_WAIT(0); }
        __syncthreads();

        const uint32_t stb = sm_base + (ch & 1) * STG_BYTES;
        #pragma unroll
        for (int ks = 0; ks < 2; ks++) {
            const int kk = ks * 16;
            uint32_t afh[2][4], afl[2][4];
            #pragma unroll
            for (int mt = 0; mt < 2; mt++) {
                uint32_t aoff = (uint32_t)((wm * 32 + mt * 16 + (lane & 15)) * SKA
                                           + kk + ((lane >> 4) << 3)) * 2u;
                ldsm_x4(afh[mt], stb + aoff);
                ldsm_x4(afl[mt], stb + OFF_AL + aoff);
            }
            uint32_t bfh[4][2], bfl[4][2];
            #pragma unroll
            for (int p = 0; p < 2; p++) {
                uint32_t boff = (uint32_t)((kk + (lane & 15)) * SKB
                                           + wn * 32 + p * 16 + ((lane >> 4) << 3)) * 2u;
                uint32_t r[4];
                ldsm_x4_t(r, stb + OFF_BH + boff);
                bfh[p * 2][0] = r[0]; bfh[p * 2][1] = r[1];
                bfh[p * 2 + 1][0] = r[2]; bfh[p * 2 + 1][1] = r[3];
                ldsm_x4_t(r, stb + OFF_BL + boff);
                bfl[p * 2][0] = r[0]; bfl[p * 2][1] = r[1];
                bfl[p * 2 + 1][0] = r[2]; bfl[p * 2 + 1][1] = r[3];
            }
            #pragma unroll
            for (int mt = 0; mt < 2; mt++)
                #pragma unroll
                for (int nt = 0; nt < 4; nt++) {
                    mma_bf16(acc[mt][nt], afh[mt], bfh[nt][0], bfh[nt][1]);
                    mma_bf16(acc[mt][nt], afh[mt], bfl[nt][0], bfl[nt][1]);
                    mma_bf16(acc[mt][nt], afl[mt], bfh[nt][0], bfh[nt][1]);
                }
        }
        __syncthreads();
        if (ch + 2 < 8) issue(ch + 2);
    }

    const int mat = m0g >> 8;
    float* outp = (mat == 0) ? g_q : (mat == 1) ? g_k : g_v;
    const int orow = (m0g & 255) + wm * 32;
    #pragma unroll
    for (int mt = 0; mt < 2; mt++) {
        int o = orow + mt * 16 + (lane >> 2);
        #pragma unroll
        for (int nt = 0; nt < 4; nt++) {
            int n = n0 + wn * 32 + nt * 8 + ((lane & 3) << 1);
            float* og = outp + ((size_t)(b * CC + o)) * HWN + n;
            *(float2*)og = make_float2(acc[mt][nt][0], acc[mt][nt][1]);
            *(float2*)(og + 8 * HWN) = make_float2(acc[mt][nt][2], acc[mt][nt][3]);
        }
    }
}

// ---------------------------------------------------------------------------
// Windowed softmax attention: persistent blocks, vectorized smem reads
// (exact R14 best version). grid 592; resets g_bar via the plane-0 stealer.
// ---------------------------------------------------------------------------
__global__ __launch_bounds__(256) void attn_kernel(
    const float* __restrict__ rel_h,
    const float* __restrict__ rel_w,
    float* __restrict__ out)
{
    __shared__ __align__(16) float ks[PHW2];
    __shared__ __align__(16) float vs[PHW2];
    __shared__ float brow_s[8];
    __shared__ int s_p;

    const int tid = threadIdx.x;
    const int p0 = tid * 4;
    const int h  = p0 >> 5;
    const int w0 = p0 & 31;
    const int pi0 = (h + 3) * PW2 + (w0 + 3);

    {
        const float4 z = make_float4(0.f, 0.f, 0.f, 0.f);
        for (int i = tid; i < PHW2 / 4; i += 256) {
            ((float4*)ks)[i] = z;
            ((float4*)vs)[i] = z;
        }
    }

    const float LOG2E = 1.4426950408889634f;

    for (;;) {
        __syncthreads();
        if (tid == 0) s_p = atomicAdd(&g_attn_ctr, 1);
        __syncthreads();
        const int p = s_p;
        if (p >= NP) break;
        if (p == 0 && tid == 0) g_bar = 0;   // reset fused-gemm barrier for next call

        const int c = p & 255;
        const bool hsel = (c < CC / 2);

        if (tid < KW)
            brow_s[tid] = hsel ? rel_h[c * KW + tid] : rel_w[(c - CC / 2) * KW + tid];

        float4 k4 = *(const float4*)(g_k + ((size_t)p) * HWN + p0);
        float4 v4 = *(const float4*)(g_v + ((size_t)p) * HWN + p0);
        ks[pi0 + 0] = k4.x; ks[pi0 + 1] = k4.y; ks[pi0 + 2] = k4.z; ks[pi0 + 3] = k4.w;
        vs[pi0 + 0] = v4.x; vs[pi0 + 1] = v4.y; vs[pi0 + 2] = v4.z; vs[pi0 + 3] = v4.w;

        float4 qv = *(const float4*)(g_q + ((size_t)p) * HWN + p0);

        __syncthreads();

        float q2[4] = { qv.x * LOG2E, qv.y * LOG2E, qv.z * LOG2E, qv.w * LOG2E };
        float acc[4] = {0.f, 0.f, 0.f, 0.f};
        float sum[4] = {0.f, 0.f, 0.f, 0.f};

        if (hsel) {
            #pragma unroll
            for (int u = 0; u < KW; u++) {
                const int rbase = (h + u) * PW2 + w0;
                float4 ka = *(const float4*)&ks[rbase];
                float4 kb = *(const float4*)&ks[rbase + 4];
                float2 kc = *(const float2*)&ks[rbase + 8];
                float4 va = *(const float4*)&vs[rbase];
                float4 vb = *(const float4*)&vs[rbase + 4];
                float2 vc = *(const float2*)&vs[rbase + 8];
                float kr[10] = { ka.x, ka.y, ka.z, ka.w, kb.x, kb.y, kb.z, kb.w, kc.x, kc.y };
                float vr[10] = { va.x, va.y, va.z, va.w, vb.x, vb.y, vb.z, vb.w, vc.x, vc.y };
                const float bu = brow_s[u];
                float qbu[4];
                #pragma unroll
                for (int jj = 0; jj < 4; jj++) qbu[jj] = q2[jj] * bu;
                #pragma unroll
                for (int v = 0; v < KW; v++) {
                    #pragma unroll
                    for (int jj = 0; jj < 4; jj++) {
                        float t = fmaf(q2[jj], kr[v + jj], qbu[jj]);
                        float e = ex2f(t);
                        sum[jj] += e;
                        acc[jj]  = fmaf(e, vr[v + jj], acc[jj]);
                    }
                }
            }
        } else {
            float qb[4][KW];
            #pragma unroll
            for (int jj = 0; jj < 4; jj++)
                #pragma unroll
                for (int i = 0; i < KW; i++)
                    qb[jj][i] = q2[jj] * brow_s[i];
            #pragma unroll
            for (int u = 0; u < KW; u++) {
                const int rbase = (h + u) * PW2 + w0;
                float4 ka = *(const float4*)&ks[rbase];
                float4 kb = *(const float4*)&ks[rbase + 4];
                float2 kc = *(const float2*)&ks[rbase + 8];
                float4 va = *(const float4*)&vs[rbase];
                float4 vb = *(const float4*)&vs[rbase + 4];
                float2 vc = *(const float2*)&vs[rbase + 8];
                float kr[10] = { ka.x, ka.y, ka.z, ka.w, kb.x, kb.y, kb.z, kb.w, kc.x, kc.y };
                float vr[10] = { va.x, va.y, va.z, va.w, vb.x, vb.y, vb.z, vb.w, vc.x, vc.y };
                #pragma unroll
                for (int v = 0; v < KW; v++) {
                    #pragma unroll
                    for (int jj = 0; jj < 4; jj++) {
                        float t = fmaf(q2[jj], kr[v + jj], qb[jj][v]);
                        float e = ex2f(t);
                        sum[jj] += e;
                        acc[jj]  = fmaf(e, vr[v + jj], acc[jj]);
                    }
                }
            }
        }

        float* og = out + ((size_t)p) * HWN + p0;
        float4 r;
        r.x = __fdividef(acc[0], sum[0]);
        r.y = __fdividef(acc[1], sum[1]);
        r.z = __fdividef(acc[2], sum[2]);
        r.w = __fdividef(acc[3], sum[3]);
        *(float4*)og = r;
    }
}

// ---------------------------------------------------------------------------
extern "C" void kernel_launch(void* const* d_in, const int* in_sizes, int n_in,
                              void* d_out, int out_size)
{
    const float* x     = (const float*)d_in[0];
    const float* wq    = (const float*)d_in[1];
    const float* wk    = (const float*)d_in[2];
    const float* wv    = (const float*)d_in[3];
    const float* rel_h = (const float*)d_in[4];
    const float* rel_w = (const float*)d_in[5];
    float* out = (float*)d_out;

    cudaFuncSetAttribute(qkv_fused_kernel, cudaFuncAttributeMaxDynamicSharedMemorySize,
                         SMEM_TOTAL);

    dim3 gg(96, BB);
    qkv_fused_kernel<<<gg, 256, SMEM_TOTAL>>>(x, wq, wk, wv);

    attn_kernel<<<592, 256>>>(rel_h, rel_w, out);
}

// round 17
// speedup vs baseline: 1.0023x; 1.0023x over previous
#include <cuda_runtime.h>
#include <cuda_bf16.h>
#include <cstdint>

// Problem constants
#define KW 7
#define CC 256
#define BB 4
#define HWN 1024          // 32*32
#define NP (BB * CC)      // 1024 planes
#define PW2 40            // padded smem row stride (floats)
#define PHW2 (38 * PW2)   // 1520 floats per plane

// Scratch (device globals)
__device__ float g_q[BB * CC * HWN];
__device__ float g_k[BB * CC * HWN];
__device__ float g_v[BB * CC * HWN];
__device__ __nv_bfloat16 g_Whi[3 * 256 * 256];
__device__ __nv_bfloat16 g_Wlo[3 * 256 * 256];
__device__ __nv_bfloat16 g_Xhi[BB * 256 * 1024];
__device__ __nv_bfloat16 g_Xlo[BB * 256 * 1024];
__device__ int g_attn_ctr;      // reset pre-barrier each call
__device__ int g_done[BB];      // per-batch gemm-tile completion; reset pre-barrier
__device__ int g_bar;           // epoch barrier (monotone, never reset)

// ---------------------------------------------------------------------------
// helpers
// ---------------------------------------------------------------------------
__device__ __forceinline__ uint32_t smem_u32(const void* p) {
    uint32_t a;
    asm("{ .reg .u64 t; cvta.to.shared.u64 t, %1; cvt.u32.u64 %0, t; }" : "=r"(a) : "l"(p));
    return a;
}
__device__ __forceinline__ void ldsm_x4(uint32_t r[4], uint32_t addr) {
    asm volatile("ldmatrix.sync.aligned.m8n8.x4.shared.b16 {%0,%1,%2,%3}, [%4];"
                 : "=r"(r[0]), "=r"(r[1]), "=r"(r[2]), "=r"(r[3]) : "r"(addr));
}
__device__ __forceinline__ void ldsm_x4_t(uint32_t r[4], uint32_t addr) {
    asm volatile("ldmatrix.sync.aligned.m8n8.x4.trans.shared.b16 {%0,%1,%2,%3}, [%4];"
                 : "=r"(r[0]), "=r"(r[1]), "=r"(r[2]), "=r"(r[3]) : "r"(addr));
}
__device__ __forceinline__ void mma_bf16(float c[4], const uint32_t a[4],
                                         uint32_t b0, uint32_t b1) {
    asm volatile(
        "mma.sync.aligned.m16n8k16.row.col.f32.bf16.bf16.f32 "
        "{%0,%1,%2,%3}, {%4,%5,%6,%7}, {%8,%9}, {%0,%1,%2,%3};"
        : "+f"(c[0]), "+f"(c[1]), "+f"(c[2]), "+f"(c[3])
        : "r"(a[0]), "r"(a[1]), "r"(a[2]), "r"(a[3]), "r"(b0), "r"(b1));
}
__device__ __forceinline__ void split_bf(float a, __nv_bfloat16& h, __nv_bfloat16& l) {
    h = __float2bfloat16(a);
    l = __float2bfloat16(a - __bfloat162float(h));
}
__device__ __forceinline__ uint32_t pack2(__nv_bfloat16 a, __nv_bfloat16 b) {
    __nv_bfloat162 t; t.x = a; t.y = b;
    return *(uint32_t*)&t;
}
#define CP_ASYNC16(dst, src) \
    asm volatile("cp.async.cg.shared.global [%0], [%1], 16;" :: "r"(dst), "l"(src))
#define CP_COMMIT() asm volatile("cp.async.commit_group;" ::: "memory")
#define CP_WAIT(N)  asm volatile("cp.async.wait_group %0;" :: "n"(N) : "memory")

__device__ __forceinline__ float ex2f(float x) {
    float y;
    asm("ex2.approx.ftz.f32 %0, %1;" : "=f"(y) : "f"(x));
    return y;
}

// ---------------------------------------------------------------------------
// Monolithic persistent kernel: convert -> epoch barrier -> 1 GEMM tile/CTA
// -> fence+done[b] -> attn plane-stealing gated on done[batch].
// grid (96, 4) = 384 CTAs, 3/SM @ 59KB smem -> all resident (384 <= 444).
// ---------------------------------------------------------------------------
#define SKA 48
#define SKB 136
#define OFF_AL 6144
#define OFF_BH 12288
#define OFF_BL 20992
#define STG_BYTES 29696
#define SMEM_TOTAL (2 * STG_BYTES)
#define N_X4 262144      // x float4 count
#define N_TOT 311296     // + W float4 count (49152)
#define N_THR 98304      // 384 * 256

__global__ __launch_bounds__(256, 3) void mono_kernel(
    const float* __restrict__ x,
    const float* __restrict__ wq,
    const float* __restrict__ wk,
    const float* __restrict__ wv,
    const float* __restrict__ rel_h,
    const float* __restrict__ rel_w,
    float* __restrict__ out)
{
    extern __shared__ char sm[];
    __shared__ float brow_s[8];
    __shared__ int s_p;
    const uint32_t sm_base = smem_u32(sm);
    const int tid = threadIdx.x;
    const int bid = blockIdx.y * 96 + blockIdx.x;   // 0..383

    // ===== Phase A: convert (grid-stride) + counter resets =====
    if (bid == 0 && tid == 0) {
        g_attn_ctr = 0;
        g_done[0] = 0; g_done[1] = 0; g_done[2] = 0; g_done[3] = 0;
    }
    for (int i = bid * 256 + tid; i < N_TOT; i += N_THR) {
        __nv_bfloat16 h0, l0, h1, l1, h2, l2, h3, l3;
        if (i < N_X4) {
            float4 v = ((const float4*)x)[i];
            split_bf(v.x, h0, l0); split_bf(v.y, h1, l1);
            split_bf(v.z, h2, l2); split_bf(v.w, h3, l3);
            int base = i * 4;
            *(uint2*)&g_Xhi[base] = make_uint2(pack2(h0, h1), pack2(h2, h3));
            *(uint2*)&g_Xlo[base] = make_uint2(pack2(l0, l1), pack2(l2, l3));
        } else {
            int i4 = i - N_X4;
            int mat = i4 >> 14;
            int off4 = i4 & 16383;
            const float* Wp = (mat == 0) ? wq : (mat == 1) ? wk : wv;
            float4 v = ((const float4*)Wp)[off4];
            split_bf(v.x, h0, l0); split_bf(v.y, h1, l1);
            split_bf(v.z, h2, l2); split_bf(v.w, h3, l3);
            int base = i4 * 4;
            *(uint2*)&g_Whi[base] = make_uint2(pack2(h0, h1), pack2(h2, h3));
            *(uint2*)&g_Wlo[base] = make_uint2(pack2(l0, l1), pack2(l2, l3));
        }
    }

    // ===== Phase A2: epoch barrier (all 384 CTAs resident; monotone ctr) =====
    __threadfence();
    __syncthreads();
    if (tid == 0) {
        int ticket = atomicAdd(&g_bar, 1);
        int target = (ticket / 384) * 384 + 384;
        volatile int* vb = &g_bar;
        while (*vb < target) __nanosleep(128);
    }
    __syncthreads();

    // ===== Phase B: one GEMM tile per CTA (static = bid) =====
    {
        const int wid  = tid >> 5;
        const int lane = tid & 31;
        const int wm   = wid >> 2;
        const int wn   = wid & 3;
        const int b    = blockIdx.y;
        const int m0g  = (blockIdx.x >> 3) * 64;
        const int n0   = (blockIdx.x & 7) * 128;

        const int ar  = tid >> 2;
        const int ac  = (tid & 3) << 3;
        const int br  = tid >> 4;
        const int bc  = (tid & 15) << 3;

        const __nv_bfloat16* AgH = g_Whi + (size_t)(m0g + ar) * 256 + ac;
        const __nv_bfloat16* AgL = g_Wlo + (size_t)(m0g + ar) * 256 + ac;
        const __nv_bfloat16* BgH = g_Xhi + ((size_t)(b * 256 + br)) * 1024 + n0 + bc;
        const __nv_bfloat16* BgL = g_Xlo + ((size_t)(b * 256 + br)) * 1024 + n0 + bc;

        const uint32_t adst = (uint32_t)(ar * SKA + ac) * 2u;
        const uint32_t bdst = (uint32_t)(br * SKB + bc) * 2u;

        auto issue = [&](int ch) {
            const uint32_t stb = sm_base + (ch & 1) * STG_BYTES;
            const int k0 = ch * 32;
            CP_ASYNC16(stb + adst,          AgH + k0);
            CP_ASYNC16(stb + OFF_AL + adst, AgL + k0);
            #pragma unroll
            for (int t = 0; t < 2; t++) {
                uint32_t d = bdst + (uint32_t)(t * 16 * SKB) * 2u;
                CP_ASYNC16(stb + OFF_BH + d, BgH + (size_t)(k0 + t * 16) * 1024);
                CP_ASYNC16(stb + OFF_BL + d, BgL + (size_t)(k0 + t * 16) * 1024);
            }
            CP_COMMIT();
        };

        issue(0);
        issue(1);

        float acc[2][4][4];
        #pragma unroll
        for (int i = 0; i < 2; i++)
            #pragma unroll
            for (int j = 0; j < 4; j++)
                #pragma unroll
                for (int r = 0; r < 4; r++) acc[i][j][r] = 0.f;

        #pragma unroll
        for (int ch = 0; ch < 8; ch++) {
            if (ch < 7) { CP_WAIT(1); } else { CP_WAIT(0); }
            __syncthreads();

            const uint32_t stb = sm_base + (ch & 1) * STG_BYTES;
            #pragma unroll
            for (int ks = 0; ks < 2; ks++) {
                const int kk = ks * 16;
                uint32_t afh[2][4], afl[2][4];
                #pragma unroll
                for (int mt = 0; mt < 2; mt++) {
                    uint32_t aoff = (uint32_t)((wm * 32 + mt * 16 + (lane & 15)) * SKA
                                               + kk + ((lane >> 4) << 3)) * 2u;
                    ldsm_x4(afh[mt], stb + aoff);
                    ldsm_x4(afl[mt], stb + OFF_AL + aoff);
                }
                uint32_t bfh[4][2], bfl[4][2];
                #pragma unroll
                for (int p = 0; p < 2; p++) {
                    uint32_t boff = (uint32_t)((kk + (lane & 15)) * SKB
                                               + wn * 32 + p * 16 + ((lane >> 4) << 3)) * 2u;
                    uint32_t r[4];
                    ldsm_x4_t(r, stb + OFF_BH + boff);
                    bfh[p * 2][0] = r[0]; bfh[p * 2][1] = r[1];
                    bfh[p * 2 + 1][0] = r[2]; bfh[p * 2 + 1][1] = r[3];
                    ldsm_x4_t(r, stb + OFF_BL + boff);
                    bfl[p * 2][0] = r[0]; bfl[p * 2][1] = r[1];
                    bfl[p * 2 + 1][0] = r[2]; bfl[p * 2 + 1][1] = r[3];
                }
                #pragma unroll
                for (int mt = 0; mt < 2; mt++)
                    #pragma unroll
                    for (int nt = 0; nt < 4; nt++) {
                        mma_bf16(acc[mt][nt], afh[mt], bfh[nt][0], bfh[nt][1]);
                        mma_bf16(acc[mt][nt], afh[mt], bfl[nt][0], bfl[nt][1]);
                        mma_bf16(acc[mt][nt], afl[mt], bfh[nt][0], bfh[nt][1]);
                    }
            }
            __syncthreads();
            if (ch + 2 < 8) issue(ch + 2);
        }

        const int mat = m0g >> 8;
        float* outp = (mat == 0) ? g_q : (mat == 1) ? g_k : g_v;
        const int orow = (m0g & 255) + wm * 32;
        #pragma unroll
        for (int mt = 0; mt < 2; mt++) {
            int o = orow + mt * 16 + (lane >> 2);
            #pragma unroll
            for (int nt = 0; nt < 4; nt++) {
                int n = n0 + wn * 32 + nt * 8 + ((lane & 3) << 1);
                float* og = outp + ((size_t)(b * CC + o)) * HWN + n;
                *(float2*)og = make_float2(acc[mt][nt][0], acc[mt][nt][1]);
                *(float2*)(og + 8 * HWN) = make_float2(acc[mt][nt][2], acc[mt][nt][3]);
            }
        }
        __threadfence();
        __syncthreads();
        if (tid == 0) atomicAdd(&g_done[b], 1);
    }

    // ===== Phase C: attention (smem reuse; done[b]-gated plane stealing) =====
    float* ks = (float*)sm;
    float* vs = ks + PHW2;
    const int p0 = tid * 4;
    const int h  = p0 >> 5;
    const int w0 = p0 & 31;
    const int pi0 = (h + 3) * PW2 + (w0 + 3);

    __syncthreads();   // gemm smem use done before reuse
    {
        const float4 z = make_float4(0.f, 0.f, 0.f, 0.f);
        for (int i = tid; i < PHW2 / 4; i += 256) {
            ((float4*)ks)[i] = z;
            ((float4*)vs)[i] = z;
        }
    }

    const float LOG2E = 1.4426950408889634f;

    for (;;) {
        __syncthreads();
        if (tid == 0) s_p = atomicAdd(&g_attn_ctr, 1);
        __syncthreads();
        const int p = s_p;
        if (p >= NP) break;

        const int c = p & 255;
        const bool hsel = (c < CC / 2);
        const int bb = p >> 8;

        if (tid == 0) {
            volatile int* dc = &g_done[bb];
            while (*dc < 96) __nanosleep(128);
        }
        if (tid < KW)
            brow_s[tid] = hsel ? rel_h[c * KW + tid] : rel_w[(c - CC / 2) * KW + tid];
        __syncthreads();   // gate satisfied + brow ready

        float4 k4 = __ldcg((const float4*)(g_k + ((size_t)p) * HWN + p0));
        float4 v4 = __ldcg((const float4*)(g_v + ((size_t)p) * HWN + p0));
        ks[pi0 + 0] = k4.x; ks[pi0 + 1] = k4.y; ks[pi0 + 2] = k4.z; ks[pi0 + 3] = k4.w;
        vs[pi0 + 0] = v4.x; vs[pi0 + 1] = v4.y; vs[pi0 + 2] = v4.z; vs[pi0 + 3] = v4.w;

        float4 qv = __ldcg((const float4*)(g_q + ((size_t)p) * HWN + p0));

        __syncthreads();

        float q2[4] = { qv.x * LOG2E, qv.y * LOG2E, qv.z * LOG2E, qv.w * LOG2E };
        float acc[4] = {0.f, 0.f, 0.f, 0.f};
        float sum[4] = {0.f, 0.f, 0.f, 0.f};

        if (hsel) {
            #pragma unroll
            for (int u = 0; u < KW; u++) {
                const int rbase = (h + u) * PW2 + w0;
                float4 ka = *(const float4*)&ks[rbase];
                float4 kb = *(const float4*)&ks[rbase + 4];
                float2 kc = *(const float2*)&ks[rbase + 8];
                float4 va = *(const float4*)&vs[rbase];
                float4 vb = *(const float4*)&vs[rbase + 4];
                float2 vc = *(const float2*)&vs[rbase + 8];
                float kr[10] = { ka.x, ka.y, ka.z, ka.w, kb.x, kb.y, kb.z, kb.w, kc.x, kc.y };
                float vr[10] = { va.x, va.y, va.z, va.w, vb.x, vb.y, vb.z, vb.w, vc.x, vc.y };
                const float bu = brow_s[u];
                float qbu[4];
                #pragma unroll
                for (int jj = 0; jj < 4; jj++) qbu[jj] = q2[jj] * bu;
                #pragma unroll
                for (int v = 0; v < KW; v++) {
                    #pragma unroll
                    for (int jj = 0; jj < 4; jj++) {
                        float t = fmaf(q2[jj], kr[v + jj], qbu[jj]);
                        float e = ex2f(t);
                        sum[jj] += e;
                        acc[jj]  = fmaf(e, vr[v + jj], acc[jj]);
                    }
                }
            }
        } else {
            float qb[4][KW];
            #pragma unroll
            for (int jj = 0; jj < 4; jj++)
                #pragma unroll
                for (int i = 0; i < KW; i++)
                    qb[jj][i] = q2[jj] * brow_s[i];
            #pragma unroll
            for (int u = 0; u < KW; u++) {
                const int rbase = (h + u) * PW2 + w0;
                float4 ka = *(const float4*)&ks[rbase];
                float4 kb = *(const float4*)&ks[rbase + 4];
                float2 kc = *(const float2*)&ks[rbase + 8];
                float4 va = *(const float4*)&vs[rbase];
                float4 vb = *(const float4*)&vs[rbase + 4];
                float2 vc = *(const float2*)&vs[rbase + 8];
                float kr[10] = { ka.x, ka.y, ka.z, ka.w, kb.x, kb.y, kb.z, kb.w, kc.x, kc.y };
                float vr[10] = { va.x, va.y, va.z, va.w, vb.x, vb.y, vb.z, vb.w, vc.x, vc.y };
                #pragma unroll
                for (int v = 0; v < KW; v++) {
                    #pragma unroll
                    for (int jj = 0; jj < 4; jj++) {
                        float t = fmaf(q2[jj], kr[v + jj], qb[jj][v]);
                        float e = ex2f(t);
                        sum[jj] += e;
                        acc[jj]  = fmaf(e, vr[v + jj], acc[jj]);
                    }
                }
            }
        }

        float* og = out + ((size_t)p) * HWN + p0;
        float4 r;
        r.x = __fdividef(acc[0], sum[0]);
        r.y = __fdividef(acc[1], sum[1]);
        r.z = __fdividef(acc[2], sum[2]);
        r.w = __fdividef(acc[3], sum[3]);
        *(float4*)og = r;
    }
}

// ---------------------------------------------------------------------------
extern "C" void kernel_launch(void* const* d_in, const int* in_sizes, int n_in,
                              void* d_out, int out_size)
{
    const float* x     = (const float*)d_in[0];
    const float* wq    = (const float*)d_in[1];
    const float* wk    = (const float*)d_in[2];
    const float* wv    = (const float*)d_in[3];
    const float* rel_h = (const float*)d_in[4];
    const float* rel_w = (const float*)d_in[5];
    float* out = (float*)d_out;

    cudaFuncSetAttribute(mono_kernel, cudaFuncAttributeMaxDynamicSharedMemorySize,
                         SMEM_TOTAL);

    dim3 gg(96, BB);
    mono_kernel<<<gg, 256, SMEM_TOTAL>>>(x, wq, wk, wv, rel_h, rel_w, out);
}